// round 13
// baseline (speedup 1.0000x reference)
#include <cuda_runtime.h>
#include <cuda_bf16.h>
#include <cstdint>
#include <cstddef>

#define HW 16384
#define NCHW 4194304
#define LWBF 204800            // bf16 per layer-dir weight blob
#define BBASE 63360            // A slab bytes (2 halves x 5 x 132 x 24ci x 2B)
#define DSMEM 104320           // 63360 (A) + 40960 (B group: 10 taps)
typedef uint32_t u32;
typedef __nv_bfloat16 bf;

// channel-last [n][y][x][c] hi/lo activation tensors
__device__ bf g_Ah[NCHW], g_Al[NCHW], g_Bh[NCHW], g_Bl[NCHW];
__device__ float g_T[3ull * NCHW];   // t0..t2, channel-last fp32
__device__ bf g_wbf[6 * LWBF];       // [ld6][chunk4][tap25][half2][co64][ci16]
__device__ float g_w0[1600];         // conv0 [uv][co]
__device__ float g_w0b[1600];        // final convT [a][u][v] flipped
__device__ float g_actp[20480];      // [l4][c64][80], data at +8

// ---- helpers -------------------------------------------------------------
__device__ __forceinline__ u32 s2u(const void* p) {
    u32 a; asm("{.reg .u64 t; cvta.to.shared.u64 t,%1; cvt.u32.u64 %0,t;}" : "=r"(a) : "l"(p));
    return a;
}
__device__ __forceinline__ void ldsm4(u32* r, u32 a) {
    asm volatile("ldmatrix.sync.aligned.m8n8.x4.shared.b16 {%0,%1,%2,%3},[%4];"
                 : "=r"(r[0]), "=r"(r[1]), "=r"(r[2]), "=r"(r[3]) : "r"(a));
}
__device__ __forceinline__ void mma16816(float* d, const u32* a, const u32* b) {
    asm volatile("mma.sync.aligned.m16n8k16.row.col.f32.bf16.bf16.f32 "
                 "{%0,%1,%2,%3},{%4,%5,%6,%7},{%8,%9},{%0,%1,%2,%3};"
                 : "+f"(d[0]), "+f"(d[1]), "+f"(d[2]), "+f"(d[3])
                 : "r"(a[0]), "r"(a[1]), "r"(a[2]), "r"(a[3]), "r"(b[0]), "r"(b[1]));
}

// ---- RBF activation, windowed |k|<=6 recurrence (verified R2) ------------
__device__ __forceinline__ float act_fwd(float v, const float* __restrict__ wr) {
    float pf = rintf((v + 310.f) * 0.1f); pf = fminf(fmaxf(pf, 0.f), 62.f);
    float d0 = v + 310.f - 10.f * pf; d0 = fminf(fmaxf(d0, -55.f), 55.f);
    float a = __expf(0.1f * d0), ai = __expf(-0.1f * d0), E0 = __expf(-0.005f * d0 * d0);
    const float* w = wr + (int)pf;
    const float CK[7] = {0.f, 0.60653066f, 0.22313016f, 0.082084999f, 0.030197383f, 0.011108997f, 0.0040867714f};
    float s = w[0], up = 1.f, un = 1.f;
#pragma unroll
    for (int k = 1; k <= 6; k++) { up *= a * CK[k]; un *= ai * CK[k]; s += w[k] * up + w[-k] * un; }
    return E0 * s;
}
__device__ __forceinline__ float act_grad(float v, const float* __restrict__ wr) {
    float pf = rintf((v + 310.f) * 0.1f); pf = fminf(fmaxf(pf, 0.f), 62.f);
    float d0 = v + 310.f - 10.f * pf; d0 = fminf(fmaxf(d0, -55.f), 55.f);
    float a = __expf(0.1f * d0), ai = __expf(-0.1f * d0), E0 = __expf(-0.005f * d0 * d0);
    const float* w = wr + (int)pf;
    const float CK[7] = {0.f, 0.60653066f, 0.22313016f, 0.082084999f, 0.030197383f, 0.011108997f, 0.0040867714f};
    float s = w[0], s1 = 0.f, up = 1.f, un = 1.f;
#pragma unroll
    for (int k = 1; k <= 6; k++) {
        up *= a * CK[k]; un *= ai * CK[k];
        float tp = w[k] * up, tm = w[-k] * un;
        s += tp + tm; s1 += (float)k * (tp - tm);
    }
    return -0.01f * E0 * (d0 * s - 10.f * s1);
}

// ---- prep ----------------------------------------------------------------
__global__ void prep_kernel(const float* __restrict__ f0, const float* __restrict__ fr,
                            const float* __restrict__ actw) {
    int idx = blockIdx.x * 256 + threadIdx.x;
    if (idx < 307200) {
        int co = idx & 63, r = idx >> 6;
        int tap = r % 25; r /= 25;
        int ci = r & 63, l = r >> 6;
        int u = tap / 5, v = tap % 5, flip = (4 - u) * 5 + (4 - v);
        float wf = fr[((l * 64 + co) * 64 + ci) * 25 + tap];
        float wb = fr[((l * 64 + ci) * 64 + co) * 25 + flip];
        int ck = ci >> 4, c16 = ci & 15;
        size_t of = ((((size_t)(l * 4 + ck) * 25 + tap) * 2) * 64 + co) * 16 + c16;
        size_t ob = (((((size_t)(3 + l) * 4 + ck) * 25 + tap) * 2) * 64 + co) * 16 + c16;
        bf fh = __float2bfloat16_rn(wf), bh = __float2bfloat16_rn(wb);
        g_wbf[of] = fh;        g_wbf[of + 1024] = __float2bfloat16_rn(wf - __bfloat162float(fh));
        g_wbf[ob] = bh;        g_wbf[ob + 1024] = __float2bfloat16_rn(wb - __bfloat162float(bh));
    }
    if (idx < 1600) {
        int co = idx & 63, uv = idx >> 6;
        g_w0[uv * 64 + co] = f0[co * 25 + uv];
        int a = idx / 25, q = idx % 25, u = q / 5, v = q % 5;
        g_w0b[a * 25 + q] = f0[a * 25 + (4 - u) * 5 + (4 - v)];
    }
    if (idx < 20480) {
        int q = (idx % 80) - 8, lc = idx / 80;
        g_actp[idx] = (q >= 0 && q < 63) ? actw[lc * 63 + q] : 0.f;
    }
}

// ---- mma.sync conv layer (64->64, bf16 hi/lo x 3 products) ---------------
// CTA: one output row y (128 px x 64 co). Warp: 32px x 32co. 2 CTAs/SM.
// All fragment loads are full-width ldmatrix.x4 (8 LDSM/tap instead of 12):
// one B x4 covers two adjacent n-tiles (regs {0,1} / {2,3}).
template <bool BWD, bool STORE_T>
__global__ __launch_bounds__(256, 2)
void mma_conv(const bf* __restrict__ inH, const bf* __restrict__ inL,
              const bf* __restrict__ wbf, const float* __restrict__ bias,
              const float* __restrict__ actp, const float* __restrict__ tg,
              float* __restrict__ tout, bf* __restrict__ outH, bf* __restrict__ outL) {
    extern __shared__ __align__(16) char smem[];
    const int tid = threadIdx.x, w = tid >> 5, lane = tid & 31;
    const int n = blockIdx.z, y = blockIdx.x;
    const int x0 = (w & 3) * 32, co0 = (w >> 2) * 32;

    const u32 base = s2u(smem);
    u32 aSt[2][2], bSt[2][2];
#pragma unroll
    for (int h = 0; h < 2; h++) {
#pragma unroll
        for (int mt = 0; mt < 2; mt++)
            aSt[h][mt] = base + h * 31680 +
                (((x0 + 16 * mt + (lane & 15)) * 24 + ((lane >> 4) << 3)) << 1);
        // B x4 pair p covers n-tiles 2p,2p+1: lanes 0-7 (co 8..+7,k0-7),
        // 8-15 (k8-15), 16-23 (co+8,k0-7), 24-31 (co+8,k8-15)
#pragma unroll
        for (int p = 0; p < 2; p++)
            bSt[h][p] = base + BBASE + h * 2048 +
                (co0 + 16 * p + ((lane >> 4) << 3) + (lane & 7)) * 32 +
                (((lane >> 3) & 1) << 4);
    }

    float acc[2][4][4];
#pragma unroll
    for (int i = 0; i < 2; i++)
#pragma unroll
        for (int j = 0; j < 4; j++)
#pragma unroll
            for (int k = 0; k < 4; k++) acc[i][j][k] = 0.f;

    const size_t imgbase = (size_t)n * HW * 64;

    for (int ck = 0; ck < 4; ck++) {
        for (int g = 0; g < 3; g++) {
            const int t0 = g * 10, ngt = (g == 2) ? 5 : 10;
            __syncthreads();
            if (g == 0) {
                // stage A: 2640 uint4 copies (2 halves x 660 positions x 2)
                const bf* pH = inH + imgbase + ck * 16;
                const bf* pL = inL + imgbase + ck * 16;
                for (int i = tid; i < 2640; i += 256) {
                    int q = i & 1, p = i >> 1;
                    int h = (p >= 660) ? 1 : 0;
                    int pos = p - h * 660;
                    int r = pos / 132, x = pos - r * 132;
                    int gy = y + r - 2, gx = x - 2;
                    const bf* src = h ? pL : pH;
                    uint4 v;
                    if (BWD) {
                        if (gy >= 0 && gy < 128 && gx >= 0 && gx < 128)
                            v = *(const uint4*)(src + (size_t)(gy * 128 + gx) * 64 + q * 8);
                        else v = make_uint4(0, 0, 0, 0);
                    } else {
                        int cy = min(max(gy, 0), 127), cx = min(max(gx, 0), 127);
                        v = *(const uint4*)(src + (size_t)(cy * 128 + cx) * 64 + q * 8);
                    }
                    *(uint4*)(smem + h * 31680 + pos * 48 + q * 16) = v;
                }
            }
            // stage B group (ngt taps x 4096B)
            {
                const uint4* bs = (const uint4*)(wbf + (size_t)ck * 51200 + (size_t)t0 * 2048);
                uint4* bd = (uint4*)(smem + BBASE);
                const int nb = ngt * 256;
                for (int i = tid; i < nb; i += 256) bd[i] = bs[i];
            }
            __syncthreads();
#pragma unroll 1
            for (int tl = 0; tl < ngt; tl++) {
                int tap = t0 + tl;
                int u = tap / 5, v = tap - 5 * u;
                u32 sh = (u32)(u * 132 + v) * 48;
                u32 Ah0[4], Ah1[4], Al0[4], Al1[4];
                ldsm4(Ah0, aSt[0][0] + sh); ldsm4(Ah1, aSt[0][1] + sh);
                ldsm4(Al0, aSt[1][0] + sh); ldsm4(Al1, aSt[1][1] + sh);
                u32 bt = (u32)tl * 4096;
                u32 Bh[2][4], Bl[2][4];     // [pair][4 regs] -> ntile 2p: regs 0,1; 2p+1: regs 2,3
                ldsm4(Bh[0], bSt[0][0] + bt); ldsm4(Bh[1], bSt[0][1] + bt);
                ldsm4(Bl[0], bSt[1][0] + bt); ldsm4(Bl[1], bSt[1][1] + bt);
#pragma unroll
                for (int nt = 0; nt < 4; nt++) {
                    const u32* bh = &Bh[nt >> 1][(nt & 1) * 2];
                    const u32* bl = &Bl[nt >> 1][(nt & 1) * 2];
                    mma16816(acc[0][nt], Ah0, bh);
                    mma16816(acc[0][nt], Ah0, bl);
                    mma16816(acc[0][nt], Al0, bh);
                    mma16816(acc[1][nt], Ah1, bh);
                    mma16816(acc[1][nt], Ah1, bl);
                    mma16816(acc[1][nt], Al1, bh);
                }
            }
        }
    }

    // epilogue: act table into smem, then activate/gate + channel-last stores
    __syncthreads();
    float* sF = (float*)smem;
    for (int i = tid; i < 5120; i += 256) sF[i] = actp[i];
    __syncthreads();

    const int g2 = lane >> 2, t2 = (lane & 3) * 2;
#pragma unroll
    for (int mt = 0; mt < 2; mt++)
#pragma unroll
        for (int nt = 0; nt < 4; nt++) {
            const float* d = acc[mt][nt];
            int pxb = x0 + 16 * mt + g2, cb = co0 + 8 * nt + t2;
            const float* wr0 = sF + cb * 80 + 8;
            const float* wr1 = wr0 + 80;
#pragma unroll
            for (int rr = 0; rr < 2; rr++) {
                int px = pxb + rr * 8;
                float v0 = d[rr * 2 + 0], v1 = d[rr * 2 + 1];
                size_t p = ((size_t)n * HW + (size_t)y * 128 + px) * 64 + cb;
                float r0, r1;
                if (BWD) {
                    float2 tv = *(const float2*)(tg + p);
                    r0 = v0 * act_grad(tv.x, wr0);
                    r1 = v1 * act_grad(tv.y, wr1);
                } else {
                    v0 += bias[cb]; v1 += bias[cb + 1];
                    if (STORE_T) *(float2*)(tout + p) = make_float2(v0, v1);
                    r0 = act_fwd(v0, wr0);
                    r1 = act_fwd(v1, wr1);
                }
                bf h0 = __float2bfloat16_rn(r0), h1 = __float2bfloat16_rn(r1);
                __nv_bfloat162 hh; hh.x = h0; hh.y = h1;
                *(__nv_bfloat162*)(outH + p) = hh;
                __nv_bfloat162 ll;
                ll.x = __float2bfloat16_rn(r0 - __bfloat162float(h0));
                ll.y = __float2bfloat16_rn(r1 - __bfloat162float(h1));
                *(__nv_bfloat162*)(outL + p) = ll;
            }
        }
}

// ---- conv0: 1->64 scalar (rep-pad, x255, bias, t0, act), channel-last out
__global__ __launch_bounds__(256)
void conv0_kernel(const float* __restrict__ x, const float* __restrict__ bias,
                  float* __restrict__ tout, bf* __restrict__ outH, bf* __restrict__ outL) {
    __shared__ float s_w[1600], s_act[5120], s_in[432];
    const int tid = threadIdx.x, xx = tid & 31, wid = tid >> 5;
    const int n = blockIdx.z, tx0 = blockIdx.x * 32, ty0 = blockIdx.y * 8;
    for (int i = tid; i < 1600; i += 256) s_w[i] = g_w0[i];
    for (int i = tid; i < 5120; i += 256) s_act[i] = g_actp[i];
    const float* ip = x + (size_t)n * HW;
    for (int i = tid; i < 432; i += 256) {
        int py = i / 36, px = i - py * 36;
        int gy = min(max(ty0 + py - 2, 0), 127), gx = min(max(tx0 + px - 2, 0), 127);
        s_in[i] = ip[gy * 128 + gx] * 255.f;
    }
    __syncthreads();
    float acc[64];
#pragma unroll
    for (int i = 0; i < 64; i++) acc[i] = 0.f;
#pragma unroll
    for (int u = 0; u < 5; u++)
#pragma unroll
        for (int v = 0; v < 5; v++) {
            const float4* wq = (const float4*)&s_w[(u * 5 + v) * 64 + wid * 8];
            float4 wa = wq[0], wb = wq[1];
#pragma unroll
            for (int yy = 0; yy < 8; yy++) {
                float iv = s_in[(yy + u) * 36 + xx + v];
                acc[yy * 8 + 0] += iv * wa.x;  acc[yy * 8 + 1] += iv * wa.y;
                acc[yy * 8 + 2] += iv * wa.z;  acc[yy * 8 + 3] += iv * wa.w;
                acc[yy * 8 + 4] += iv * wb.x;  acc[yy * 8 + 5] += iv * wb.y;
                acc[yy * 8 + 6] += iv * wb.z;  acc[yy * 8 + 7] += iv * wb.w;
            }
        }
#pragma unroll
    for (int c = 0; c < 8; c += 2) {
        int co = wid * 8 + c;
        const float* wr0 = &s_act[co * 80 + 8];
        const float* wr1 = wr0 + 80;
        float b0 = bias[co], b1 = bias[co + 1];
#pragma unroll
        for (int yy = 0; yy < 8; yy++) {
            size_t p = ((size_t)n * HW + (size_t)(ty0 + yy) * 128 + tx0 + xx) * 64 + co;
            float v0 = acc[yy * 8 + c] + b0, v1 = acc[yy * 8 + c + 1] + b1;
            *(float2*)(tout + p) = make_float2(v0, v1);
            float r0 = act_fwd(v0, wr0), r1 = act_fwd(v1, wr1);
            bf h0 = __float2bfloat16_rn(r0), h1 = __float2bfloat16_rn(r1);
            __nv_bfloat162 hh; hh.x = h0; hh.y = h1;
            *(__nv_bfloat162*)(outH + p) = hh;
            __nv_bfloat162 ll;
            ll.x = __float2bfloat16_rn(r0 - __bfloat162float(h0));
            ll.y = __float2bfloat16_rn(r1 - __bfloat162float(h1));
            *(__nv_bfloat162*)(outL + p) = ll;
        }
    }
}

// ---- final: crop(conv_t(in, f0)) 64->1 + combine (channel-last input) ----
__global__ __launch_bounds__(256)
void final_kernel(const bf* __restrict__ inH, const bf* __restrict__ inL,
                  const float* __restrict__ xin, const float* __restrict__ yin,
                  const float* __restrict__ lam, float* __restrict__ out) {
    __shared__ float s_w[1600], s_in[16 * 432];
    const int tid = threadIdx.x, x = tid & 31, yy = tid >> 5;
    const int n = blockIdx.z, tx0 = blockIdx.x * 32, ty0 = blockIdx.y * 8;
    for (int i = tid; i < 1600; i += 256) s_w[i] = g_w0b[i];
    float acc = 0.f;
    for (int c0 = 0; c0 < 64; c0 += 16) {
        __syncthreads();
        for (int i = tid; i < 6912; i += 256) {
            int cc = i & 15, j = i >> 4;
            int py = j / 36, px = j - py * 36;
            int gy = ty0 + py - 2, gx = tx0 + px - 2;
            float vv = 0.f;
            if (gy >= 0 && gy < 128 && gx >= 0 && gx < 128) {
                size_t o = ((size_t)n * HW + (size_t)gy * 128 + gx) * 64 + c0 + cc;
                vv = __bfloat162float(inH[o]) + __bfloat162float(inL[o]);
            }
            s_in[cc * 432 + j] = vv;
        }
        __syncthreads();
#pragma unroll
        for (int cc = 0; cc < 16; cc++) {
            const float* wp = &s_w[(c0 + cc) * 25];
            const float* pin = s_in + cc * 432;
#pragma unroll
            for (int u = 0; u < 5; u++)
#pragma unroll
                for (int v = 0; v < 5; v++)
                    acc += pin[(yy + u) * 36 + x + v] * wp[u * 5 + v];
        }
    }
    size_t idx = (size_t)n * HW + (size_t)(ty0 + yy) * 128 + tx0 + x;
    float xv = xin[idx], yv = yin[idx];
    out[idx] = xv - acc * (1.f / 255.f) - __expf(lam[0]) * (xv - yv);
}

// ---- launch --------------------------------------------------------------
extern "C" void kernel_launch(void* const* d_in, const int* in_sizes, int n_in,
                              void* d_out, int out_size) {
    const float *x = nullptr, *y = nullptr, *lam = nullptr, *f0 = nullptr,
                *fr = nullptr, *bias = nullptr, *actw = nullptr;
    for (int i = 0; i < n_in; i++) {
        const float* p = (const float*)d_in[i];
        switch (in_sizes[i]) {
            case 65536: if (!x) x = p; else y = p; break;
            case 1: lam = p; break;
            case 1600: f0 = p; break;
            case 307200: fr = p; break;
            case 256: bias = p; break;
            case 16128: actw = p; break;
            default: break;
        }
    }
    void *pAh, *pAl, *pBh, *pBl, *pT, *pW, *pact;
    cudaGetSymbolAddress(&pAh, g_Ah); cudaGetSymbolAddress(&pAl, g_Al);
    cudaGetSymbolAddress(&pBh, g_Bh); cudaGetSymbolAddress(&pBl, g_Bl);
    cudaGetSymbolAddress(&pT, g_T);   cudaGetSymbolAddress(&pW, g_wbf);
    cudaGetSymbolAddress(&pact, g_actp);
    bf *Ah = (bf*)pAh, *Al = (bf*)pAl, *Bh = (bf*)pBh, *Bl = (bf*)pBl;
    float *T = (float*)pT, *act = (float*)pact;
    bf *W = (bf*)pW;

    cudaFuncSetAttribute(mma_conv<false, true >, cudaFuncAttributeMaxDynamicSharedMemorySize, DSMEM);
    cudaFuncSetAttribute(mma_conv<false, false>, cudaFuncAttributeMaxDynamicSharedMemorySize, DSMEM);
    cudaFuncSetAttribute(mma_conv<true,  false>, cudaFuncAttributeMaxDynamicSharedMemorySize, DSMEM);

    dim3 gs(4, 16, 4), gm(128, 1, 4), blk(256);
    prep_kernel<<<1200, 256>>>(f0, fr, actw);
    conv0_kernel<<<gs, blk>>>(x, bias, T, Ah, Al);
    // forward layers 1..3 (weights ld0..2)
    mma_conv<false, true ><<<gm, blk, DSMEM>>>(Ah, Al, W,            bias + 64,  act + 5120,     nullptr, T + (size_t)NCHW, Bh, Bl);
    mma_conv<false, true ><<<gm, blk, DSMEM>>>(Bh, Bl, W + LWBF,     bias + 128, act + 2 * 5120, nullptr, T + 2ull * NCHW,  Ah, Al);
    mma_conv<false, false><<<gm, blk, DSMEM>>>(Ah, Al, W + 2 * LWBF, bias + 192, act + 3 * 5120, nullptr, nullptr,          Bh, Bl);
    // backward: convT(w3) gate t2, convT(w2) gate t1, convT(w1) gate t0
    mma_conv<true, false><<<gm, blk, DSMEM>>>(Bh, Bl, W + 5 * LWBF, nullptr, act + 2 * 5120, T + 2ull * NCHW,  nullptr, Ah, Al);
    mma_conv<true, false><<<gm, blk, DSMEM>>>(Ah, Al, W + 4 * LWBF, nullptr, act + 5120,     T + (size_t)NCHW, nullptr, Bh, Bl);
    mma_conv<true, false><<<gm, blk, DSMEM>>>(Bh, Bl, W + 3 * LWBF, nullptr, act,            T,                nullptr, Ah, Al);
    final_kernel<<<gs, blk>>>(Ah, Al, x, y, lam, (float*)d_out);
}

// round 14
// speedup vs baseline: 1.0523x; 1.0523x over previous
#include <cuda_runtime.h>
#include <cuda_bf16.h>
#include <cstdint>
#include <cstddef>

#define HW 16384
#define NCHW 4194304
#define LWBF 204800            // bf16 per layer-dir weight blob
#define BBASE 63360            // A slab bytes (2 halves x 5 x 132 x 24ci x 2B)
#define DSMEM 104320           // 63360 (A) + 40960 (B group: 10 taps)
typedef uint32_t u32;
typedef __nv_bfloat16 bf;

// channel-last [n][y][x][c] hi/lo activation tensors
__device__ bf g_Ah[NCHW], g_Al[NCHW], g_Bh[NCHW], g_Bl[NCHW];
__device__ float g_T[3ull * NCHW];   // t0..t2, channel-last fp32
__device__ bf g_wbf[6 * LWBF];       // [ld6][chunk4][tap25][half2][co64][ci16]
__device__ float g_w0[1600];         // conv0 [uv][co]
__device__ float g_w0b[1600];        // final convT [a][u][v] flipped
__device__ float g_actp[20480];      // [l4][c64][80], data at +8

// ---- helpers -------------------------------------------------------------
__device__ __forceinline__ u32 s2u(const void* p) {
    u32 a; asm("{.reg .u64 t; cvta.to.shared.u64 t,%1; cvt.u32.u64 %0,t;}" : "=r"(a) : "l"(p));
    return a;
}
__device__ __forceinline__ void ldsm4(u32* r, u32 a) {
    asm volatile("ldmatrix.sync.aligned.m8n8.x4.shared.b16 {%0,%1,%2,%3},[%4];"
                 : "=r"(r[0]), "=r"(r[1]), "=r"(r[2]), "=r"(r[3]) : "r"(a));
}
__device__ __forceinline__ void mma16816(float* d, const u32* a, const u32* b) {
    asm volatile("mma.sync.aligned.m16n8k16.row.col.f32.bf16.bf16.f32 "
                 "{%0,%1,%2,%3},{%4,%5,%6,%7},{%8,%9},{%0,%1,%2,%3};"
                 : "+f"(d[0]), "+f"(d[1]), "+f"(d[2]), "+f"(d[3])
                 : "r"(a[0]), "r"(a[1]), "r"(a[2]), "r"(a[3]), "r"(b[0]), "r"(b[1]));
}

// ---- RBF activation, windowed |k|<=6 recurrence (verified R2) ------------
__device__ __forceinline__ float act_fwd(float v, const float* __restrict__ wr) {
    float pf = rintf((v + 310.f) * 0.1f); pf = fminf(fmaxf(pf, 0.f), 62.f);
    float d0 = v + 310.f - 10.f * pf; d0 = fminf(fmaxf(d0, -55.f), 55.f);
    float a = __expf(0.1f * d0), ai = __expf(-0.1f * d0), E0 = __expf(-0.005f * d0 * d0);
    const float* w = wr + (int)pf;
    const float CK[7] = {0.f, 0.60653066f, 0.22313016f, 0.082084999f, 0.030197383f, 0.011108997f, 0.0040867714f};
    float s = w[0], up = 1.f, un = 1.f;
#pragma unroll
    for (int k = 1; k <= 6; k++) { up *= a * CK[k]; un *= ai * CK[k]; s += w[k] * up + w[-k] * un; }
    return E0 * s;
}
__device__ __forceinline__ float act_grad(float v, const float* __restrict__ wr) {
    float pf = rintf((v + 310.f) * 0.1f); pf = fminf(fmaxf(pf, 0.f), 62.f);
    float d0 = v + 310.f - 10.f * pf; d0 = fminf(fmaxf(d0, -55.f), 55.f);
    float a = __expf(0.1f * d0), ai = __expf(-0.1f * d0), E0 = __expf(-0.005f * d0 * d0);
    const float* w = wr + (int)pf;
    const float CK[7] = {0.f, 0.60653066f, 0.22313016f, 0.082084999f, 0.030197383f, 0.011108997f, 0.0040867714f};
    float s = w[0], s1 = 0.f, up = 1.f, un = 1.f;
#pragma unroll
    for (int k = 1; k <= 6; k++) {
        up *= a * CK[k]; un *= ai * CK[k];
        float tp = w[k] * up, tm = w[-k] * un;
        s += tp + tm; s1 += (float)k * (tp - tm);
    }
    return -0.01f * E0 * (d0 * s - 10.f * s1);
}

// ---- prep ----------------------------------------------------------------
__global__ void prep_kernel(const float* __restrict__ f0, const float* __restrict__ fr,
                            const float* __restrict__ actw) {
    int idx = blockIdx.x * 256 + threadIdx.x;
    if (idx < 307200) {
        int co = idx & 63, r = idx >> 6;
        int tap = r % 25; r /= 25;
        int ci = r & 63, l = r >> 6;
        int u = tap / 5, v = tap % 5, flip = (4 - u) * 5 + (4 - v);
        float wf = fr[((l * 64 + co) * 64 + ci) * 25 + tap];
        float wb = fr[((l * 64 + ci) * 64 + co) * 25 + flip];
        int ck = ci >> 4, c16 = ci & 15;
        size_t of = ((((size_t)(l * 4 + ck) * 25 + tap) * 2) * 64 + co) * 16 + c16;
        size_t ob = (((((size_t)(3 + l) * 4 + ck) * 25 + tap) * 2) * 64 + co) * 16 + c16;
        bf fh = __float2bfloat16_rn(wf), bh = __float2bfloat16_rn(wb);
        g_wbf[of] = fh;        g_wbf[of + 1024] = __float2bfloat16_rn(wf - __bfloat162float(fh));
        g_wbf[ob] = bh;        g_wbf[ob + 1024] = __float2bfloat16_rn(wb - __bfloat162float(bh));
    }
    if (idx < 1600) {
        int co = idx & 63, uv = idx >> 6;
        g_w0[uv * 64 + co] = f0[co * 25 + uv];
        int a = idx / 25, q = idx % 25, u = q / 5, v = q % 5;
        g_w0b[a * 25 + q] = f0[a * 25 + (4 - u) * 5 + (4 - v)];
    }
    if (idx < 20480) {
        int q = (idx % 80) - 8, lc = idx / 80;
        g_actp[idx] = (q >= 0 && q < 63) ? actw[lc * 63 + q] : 0.f;
    }
}

// ---- mma.sync conv layer (64->64, bf16 hi/lo x 3 products) ---------------
// CTA: one output row y (128 px x 64 co). Warp: 32px x 32co. 2 CTAs/SM.
// B smem is bank-swizzled: within each [co64][k8x16B] 2048B block the 16B k8
// index is XORed with co bit2 -> 8-row ldmatrix phases hit 8 distinct bank
// groups (was 2-way conflicted at stride 32B).
template <bool BWD, bool STORE_T>
__global__ __launch_bounds__(256, 2)
void mma_conv(const bf* __restrict__ inH, const bf* __restrict__ inL,
              const bf* __restrict__ wbf, const float* __restrict__ bias,
              const float* __restrict__ actp, const float* __restrict__ tg,
              float* __restrict__ tout, bf* __restrict__ outH, bf* __restrict__ outL) {
    extern __shared__ __align__(16) char smem[];
    const int tid = threadIdx.x, w = tid >> 5, lane = tid & 31;
    const int n = blockIdx.z, y = blockIdx.x;
    const int x0 = (w & 3) * 32, co0 = (w >> 2) * 32;

    const u32 base = s2u(smem);
    u32 aSt[2][2], bSt[2][2];
#pragma unroll
    for (int h = 0; h < 2; h++) {
#pragma unroll
        for (int mt = 0; mt < 2; mt++)
            aSt[h][mt] = base + h * 31680 +
                (((x0 + 16 * mt + (lane & 15)) * 24 + ((lane >> 4) << 3)) << 1);
        // B x4 pair p covers n-tiles 2p,2p+1 (swizzled k8 index)
#pragma unroll
        for (int p = 0; p < 2; p++) {
            int co = co0 + 16 * p + ((lane >> 4) << 3) + (lane & 7);
            int k8 = (lane >> 3) & 1;
            bSt[h][p] = base + BBASE + h * 2048 + co * 32 +
                        ((k8 ^ ((co >> 2) & 1)) << 4);
        }
    }

    float acc[2][4][4];
#pragma unroll
    for (int i = 0; i < 2; i++)
#pragma unroll
        for (int j = 0; j < 4; j++)
#pragma unroll
            for (int k = 0; k < 4; k++) acc[i][j][k] = 0.f;

    const size_t imgbase = (size_t)n * HW * 64;

    for (int ck = 0; ck < 4; ck++) {
        for (int g = 0; g < 3; g++) {
            const int t0 = g * 10, ngt = (g == 2) ? 5 : 10;
            __syncthreads();
            if (g == 0) {
                // stage A: 2640 uint4 copies (2 halves x 660 positions x 2)
                const bf* pH = inH + imgbase + ck * 16;
                const bf* pL = inL + imgbase + ck * 16;
                for (int i = tid; i < 2640; i += 256) {
                    int q = i & 1, p = i >> 1;
                    int h = (p >= 660) ? 1 : 0;
                    int pos = p - h * 660;
                    int r = pos / 132, x = pos - r * 132;
                    int gy = y + r - 2, gx = x - 2;
                    const bf* src = h ? pL : pH;
                    uint4 v;
                    if (BWD) {
                        if (gy >= 0 && gy < 128 && gx >= 0 && gx < 128)
                            v = *(const uint4*)(src + (size_t)(gy * 128 + gx) * 64 + q * 8);
                        else v = make_uint4(0, 0, 0, 0);
                    } else {
                        int cy = min(max(gy, 0), 127), cx = min(max(gx, 0), 127);
                        v = *(const uint4*)(src + (size_t)(cy * 128 + cx) * 64 + q * 8);
                    }
                    *(uint4*)(smem + h * 31680 + pos * 48 + q * 16) = v;
                }
            }
            // stage B group (ngt taps x 4096B), swizzled within 128-uint4 blocks
            {
                const uint4* bs = (const uint4*)(wbf + (size_t)ck * 51200 + (size_t)t0 * 2048);
                uint4* bd = (uint4*)(smem + BBASE);
                const int nb = ngt * 256;
                for (int i = tid; i < nb; i += 256) {
                    int j = i & 127;
                    int js = j ^ ((j >> 3) & 1);
                    bd[(i & ~127) | js] = bs[i];
                }
            }
            __syncthreads();
#pragma unroll 1
            for (int tl = 0; tl < ngt; tl++) {
                int tap = t0 + tl;
                int u = tap / 5, v = tap - 5 * u;
                u32 sh = (u32)(u * 132 + v) * 48;
                u32 Ah0[4], Ah1[4], Al0[4], Al1[4];
                ldsm4(Ah0, aSt[0][0] + sh); ldsm4(Ah1, aSt[0][1] + sh);
                ldsm4(Al0, aSt[1][0] + sh); ldsm4(Al1, aSt[1][1] + sh);
                u32 bt = (u32)tl * 4096;
                u32 Bh[2][4], Bl[2][4];     // [pair][4 regs] -> ntile 2p: regs 0,1; 2p+1: regs 2,3
                ldsm4(Bh[0], bSt[0][0] + bt); ldsm4(Bh[1], bSt[0][1] + bt);
                ldsm4(Bl[0], bSt[1][0] + bt); ldsm4(Bl[1], bSt[1][1] + bt);
#pragma unroll
                for (int nt = 0; nt < 4; nt++) {
                    const u32* bh = &Bh[nt >> 1][(nt & 1) * 2];
                    const u32* bl = &Bl[nt >> 1][(nt & 1) * 2];
                    mma16816(acc[0][nt], Ah0, bh);
                    mma16816(acc[0][nt], Ah0, bl);
                    mma16816(acc[0][nt], Al0, bh);
                    mma16816(acc[1][nt], Ah1, bh);
                    mma16816(acc[1][nt], Ah1, bl);
                    mma16816(acc[1][nt], Al1, bh);
                }
            }
        }
    }

    // epilogue: act table into smem, then activate/gate + channel-last stores
    __syncthreads();
    float* sF = (float*)smem;
    for (int i = tid; i < 5120; i += 256) sF[i] = actp[i];
    __syncthreads();

    const int g2 = lane >> 2, t2 = (lane & 3) * 2;
#pragma unroll
    for (int mt = 0; mt < 2; mt++)
#pragma unroll
        for (int nt = 0; nt < 4; nt++) {
            const float* d = acc[mt][nt];
            int pxb = x0 + 16 * mt + g2, cb = co0 + 8 * nt + t2;
            const float* wr0 = sF + cb * 80 + 8;
            const float* wr1 = wr0 + 80;
#pragma unroll
            for (int rr = 0; rr < 2; rr++) {
                int px = pxb + rr * 8;
                float v0 = d[rr * 2 + 0], v1 = d[rr * 2 + 1];
                size_t p = ((size_t)n * HW + (size_t)y * 128 + px) * 64 + cb;
                float r0, r1;
                if (BWD) {
                    float2 tv = *(const float2*)(tg + p);
                    r0 = v0 * act_grad(tv.x, wr0);
                    r1 = v1 * act_grad(tv.y, wr1);
                } else {
                    v0 += bias[cb]; v1 += bias[cb + 1];
                    if (STORE_T) *(float2*)(tout + p) = make_float2(v0, v1);
                    r0 = act_fwd(v0, wr0);
                    r1 = act_fwd(v1, wr1);
                }
                bf h0 = __float2bfloat16_rn(r0), h1 = __float2bfloat16_rn(r1);
                __nv_bfloat162 hh; hh.x = h0; hh.y = h1;
                *(__nv_bfloat162*)(outH + p) = hh;
                __nv_bfloat162 ll;
                ll.x = __float2bfloat16_rn(r0 - __bfloat162float(h0));
                ll.y = __float2bfloat16_rn(r1 - __bfloat162float(h1));
                *(__nv_bfloat162*)(outL + p) = ll;
            }
        }
}

// ---- conv0: 1->64 scalar (rep-pad, x255, bias, t0, act), channel-last out
__global__ __launch_bounds__(256)
void conv0_kernel(const float* __restrict__ x, const float* __restrict__ bias,
                  float* __restrict__ tout, bf* __restrict__ outH, bf* __restrict__ outL) {
    __shared__ float s_w[1600], s_act[5120], s_in[432];
    const int tid = threadIdx.x, xx = tid & 31, wid = tid >> 5;
    const int n = blockIdx.z, tx0 = blockIdx.x * 32, ty0 = blockIdx.y * 8;
    for (int i = tid; i < 1600; i += 256) s_w[i] = g_w0[i];
    for (int i = tid; i < 5120; i += 256) s_act[i] = g_actp[i];
    const float* ip = x + (size_t)n * HW;
    for (int i = tid; i < 432; i += 256) {
        int py = i / 36, px = i - py * 36;
        int gy = min(max(ty0 + py - 2, 0), 127), gx = min(max(tx0 + px - 2, 0), 127);
        s_in[i] = ip[gy * 128 + gx] * 255.f;
    }
    __syncthreads();
    float acc[64];
#pragma unroll
    for (int i = 0; i < 64; i++) acc[i] = 0.f;
#pragma unroll
    for (int u = 0; u < 5; u++)
#pragma unroll
        for (int v = 0; v < 5; v++) {
            const float4* wq = (const float4*)&s_w[(u * 5 + v) * 64 + wid * 8];
            float4 wa = wq[0], wb = wq[1];
#pragma unroll
            for (int yy = 0; yy < 8; yy++) {
                float iv = s_in[(yy + u) * 36 + xx + v];
                acc[yy * 8 + 0] += iv * wa.x;  acc[yy * 8 + 1] += iv * wa.y;
                acc[yy * 8 + 2] += iv * wa.z;  acc[yy * 8 + 3] += iv * wa.w;
                acc[yy * 8 + 4] += iv * wb.x;  acc[yy * 8 + 5] += iv * wb.y;
                acc[yy * 8 + 6] += iv * wb.z;  acc[yy * 8 + 7] += iv * wb.w;
            }
        }
#pragma unroll
    for (int c = 0; c < 8; c += 2) {
        int co = wid * 8 + c;
        const float* wr0 = &s_act[co * 80 + 8];
        const float* wr1 = wr0 + 80;
        float b0 = bias[co], b1 = bias[co + 1];
#pragma unroll
        for (int yy = 0; yy < 8; yy++) {
            size_t p = ((size_t)n * HW + (size_t)(ty0 + yy) * 128 + tx0 + xx) * 64 + co;
            float v0 = acc[yy * 8 + c] + b0, v1 = acc[yy * 8 + c + 1] + b1;
            *(float2*)(tout + p) = make_float2(v0, v1);
            float r0 = act_fwd(v0, wr0), r1 = act_fwd(v1, wr1);
            bf h0 = __float2bfloat16_rn(r0), h1 = __float2bfloat16_rn(r1);
            __nv_bfloat162 hh; hh.x = h0; hh.y = h1;
            *(__nv_bfloat162*)(outH + p) = hh;
            __nv_bfloat162 ll;
            ll.x = __float2bfloat16_rn(r0 - __bfloat162float(h0));
            ll.y = __float2bfloat16_rn(r1 - __bfloat162float(h1));
            *(__nv_bfloat162*)(outL + p) = ll;
        }
    }
}

// ---- final: crop(conv_t(in, f0)) 64->1 + combine (channel-last input) ----
__global__ __launch_bounds__(256)
void final_kernel(const bf* __restrict__ inH, const bf* __restrict__ inL,
                  const float* __restrict__ xin, const float* __restrict__ yin,
                  const float* __restrict__ lam, float* __restrict__ out) {
    __shared__ float s_w[1600], s_in[16 * 432];
    const int tid = threadIdx.x, x = tid & 31, yy = tid >> 5;
    const int n = blockIdx.z, tx0 = blockIdx.x * 32, ty0 = blockIdx.y * 8;
    for (int i = tid; i < 1600; i += 256) s_w[i] = g_w0b[i];
    float acc = 0.f;
    for (int c0 = 0; c0 < 64; c0 += 16) {
        __syncthreads();
        for (int i = tid; i < 6912; i += 256) {
            int cc = i & 15, j = i >> 4;
            int py = j / 36, px = j - py * 36;
            int gy = ty0 + py - 2, gx = tx0 + px - 2;
            float vv = 0.f;
            if (gy >= 0 && gy < 128 && gx >= 0 && gx < 128) {
                size_t o = ((size_t)n * HW + (size_t)gy * 128 + gx) * 64 + c0 + cc;
                vv = __bfloat162float(inH[o]) + __bfloat162float(inL[o]);
            }
            s_in[cc * 432 + j] = vv;
        }
        __syncthreads();
#pragma unroll
        for (int cc = 0; cc < 16; cc++) {
            const float* wp = &s_w[(c0 + cc) * 25];
            const float* pin = s_in + cc * 432;
#pragma unroll
            for (int u = 0; u < 5; u++)
#pragma unroll
                for (int v = 0; v < 5; v++)
                    acc += pin[(yy + u) * 36 + x + v] * wp[u * 5 + v];
        }
    }
    size_t idx = (size_t)n * HW + (size_t)(ty0 + yy) * 128 + tx0 + x;
    float xv = xin[idx], yv = yin[idx];
    out[idx] = xv - acc * (1.f / 255.f) - __expf(lam[0]) * (xv - yv);
}

// ---- launch --------------------------------------------------------------
extern "C" void kernel_launch(void* const* d_in, const int* in_sizes, int n_in,
                              void* d_out, int out_size) {
    const float *x = nullptr, *y = nullptr, *lam = nullptr, *f0 = nullptr,
                *fr = nullptr, *bias = nullptr, *actw = nullptr;
    for (int i = 0; i < n_in; i++) {
        const float* p = (const float*)d_in[i];
        switch (in_sizes[i]) {
            case 65536: if (!x) x = p; else y = p; break;
            case 1: lam = p; break;
            case 1600: f0 = p; break;
            case 307200: fr = p; break;
            case 256: bias = p; break;
            case 16128: actw = p; break;
            default: break;
        }
    }
    void *pAh, *pAl, *pBh, *pBl, *pT, *pW, *pact;
    cudaGetSymbolAddress(&pAh, g_Ah); cudaGetSymbolAddress(&pAl, g_Al);
    cudaGetSymbolAddress(&pBh, g_Bh); cudaGetSymbolAddress(&pBl, g_Bl);
    cudaGetSymbolAddress(&pT, g_T);   cudaGetSymbolAddress(&pW, g_wbf);
    cudaGetSymbolAddress(&pact, g_actp);
    bf *Ah = (bf*)pAh, *Al = (bf*)pAl, *Bh = (bf*)pBh, *Bl = (bf*)pBl;
    float *T = (float*)pT, *act = (float*)pact;
    bf *W = (bf*)pW;

    cudaFuncSetAttribute(mma_conv<false, true >, cudaFuncAttributeMaxDynamicSharedMemorySize, DSMEM);
    cudaFuncSetAttribute(mma_conv<false, false>, cudaFuncAttributeMaxDynamicSharedMemorySize, DSMEM);
    cudaFuncSetAttribute(mma_conv<true,  false>, cudaFuncAttributeMaxDynamicSharedMemorySize, DSMEM);

    dim3 gs(4, 16, 4), gm(128, 1, 4), blk(256);
    prep_kernel<<<1200, 256>>>(f0, fr, actw);
    conv0_kernel<<<gs, blk>>>(x, bias, T, Ah, Al);
    // forward layers 1..3 (weights ld0..2)
    mma_conv<false, true ><<<gm, blk, DSMEM>>>(Ah, Al, W,            bias + 64,  act + 5120,     nullptr, T + (size_t)NCHW, Bh, Bl);
    mma_conv<false, true ><<<gm, blk, DSMEM>>>(Bh, Bl, W + LWBF,     bias + 128, act + 2 * 5120, nullptr, T + 2ull * NCHW,  Ah, Al);
    mma_conv<false, false><<<gm, blk, DSMEM>>>(Ah, Al, W + 2 * LWBF, bias + 192, act + 3 * 5120, nullptr, nullptr,          Bh, Bl);
    // backward: convT(w3) gate t2, convT(w2) gate t1, convT(w1) gate t0
    mma_conv<true, false><<<gm, blk, DSMEM>>>(Bh, Bl, W + 5 * LWBF, nullptr, act + 2 * 5120, T + 2ull * NCHW,  nullptr, Ah, Al);
    mma_conv<true, false><<<gm, blk, DSMEM>>>(Ah, Al, W + 4 * LWBF, nullptr, act + 5120,     T + (size_t)NCHW, nullptr, Bh, Bl);
    mma_conv<true, false><<<gm, blk, DSMEM>>>(Bh, Bl, W + 3 * LWBF, nullptr, act,            T,                nullptr, Ah, Al);
    final_kernel<<<gs, blk>>>(Ah, Al, x, y, lam, (float*)d_out);
}

// round 15
// speedup vs baseline: 1.0681x; 1.0149x over previous
#include <cuda_runtime.h>
#include <cuda_bf16.h>
#include <cstdint>
#include <cstddef>

#define HW 16384
#define NCHW 4194304
#define LWBF 204800            // bf16 per layer-dir weight blob
#define ABYTES 42240           // A slab: 2 halves x 5 rows x 132 px x 16ci x 2B
#define BB 42240               // B buffer offset
#define DSMEM 62720            // A (42240) + B group of 5 taps (20480)
typedef uint32_t u32;
typedef __nv_bfloat16 bf;

// channel-last [n][y][x][c] hi/lo activation tensors
__device__ bf g_Ah[NCHW], g_Al[NCHW], g_Bh[NCHW], g_Bl[NCHW];
__device__ float g_T[3ull * NCHW];   // t0..t2, channel-last fp32
__device__ bf g_wbf[6 * LWBF];       // [ld6][chunk4][tap25][half2][co64][ci16]
__device__ float g_w0[1600];         // conv0 [uv][co]
__device__ float g_w0b[1600];        // final convT [a][u][v] flipped
__device__ float g_actp[20480];      // [l4][c64][80], data at +8

// ---- helpers -------------------------------------------------------------
__device__ __forceinline__ u32 s2u(const void* p) {
    u32 a; asm("{.reg .u64 t; cvta.to.shared.u64 t,%1; cvt.u32.u64 %0,t;}" : "=r"(a) : "l"(p));
    return a;
}
__device__ __forceinline__ void ldsm4(u32* r, u32 a) {
    asm volatile("ldmatrix.sync.aligned.m8n8.x4.shared.b16 {%0,%1,%2,%3},[%4];"
                 : "=r"(r[0]), "=r"(r[1]), "=r"(r[2]), "=r"(r[3]) : "r"(a));
}
__device__ __forceinline__ void mma16816(float* d, const u32* a, const u32* b) {
    asm volatile("mma.sync.aligned.m16n8k16.row.col.f32.bf16.bf16.f32 "
                 "{%0,%1,%2,%3},{%4,%5,%6,%7},{%8,%9},{%0,%1,%2,%3};"
                 : "+f"(d[0]), "+f"(d[1]), "+f"(d[2]), "+f"(d[3])
                 : "r"(a[0]), "r"(a[1]), "r"(a[2]), "r"(a[3]), "r"(b[0]), "r"(b[1]));
}

// ---- RBF activation, windowed |k|<=6 recurrence (verified R2) ------------
__device__ __forceinline__ float act_fwd(float v, const float* __restrict__ wr) {
    float pf = rintf((v + 310.f) * 0.1f); pf = fminf(fmaxf(pf, 0.f), 62.f);
    float d0 = v + 310.f - 10.f * pf; d0 = fminf(fmaxf(d0, -55.f), 55.f);
    float a = __expf(0.1f * d0), ai = __expf(-0.1f * d0), E0 = __expf(-0.005f * d0 * d0);
    const float* w = wr + (int)pf;
    const float CK[7] = {0.f, 0.60653066f, 0.22313016f, 0.082084999f, 0.030197383f, 0.011108997f, 0.0040867714f};
    float s = w[0], up = 1.f, un = 1.f;
#pragma unroll
    for (int k = 1; k <= 6; k++) { up *= a * CK[k]; un *= ai * CK[k]; s += w[k] * up + w[-k] * un; }
    return E0 * s;
}
__device__ __forceinline__ float act_grad(float v, const float* __restrict__ wr) {
    float pf = rintf((v + 310.f) * 0.1f); pf = fminf(fmaxf(pf, 0.f), 62.f);
    float d0 = v + 310.f - 10.f * pf; d0 = fminf(fmaxf(d0, -55.f), 55.f);
    float a = __expf(0.1f * d0), ai = __expf(-0.1f * d0), E0 = __expf(-0.005f * d0 * d0);
    const float* w = wr + (int)pf;
    const float CK[7] = {0.f, 0.60653066f, 0.22313016f, 0.082084999f, 0.030197383f, 0.011108997f, 0.0040867714f};
    float s = w[0], s1 = 0.f, up = 1.f, un = 1.f;
#pragma unroll
    for (int k = 1; k <= 6; k++) {
        up *= a * CK[k]; un *= ai * CK[k];
        float tp = w[k] * up, tm = w[-k] * un;
        s += tp + tm; s1 += (float)k * (tp - tm);
    }
    return -0.01f * E0 * (d0 * s - 10.f * s1);
}

// ---- prep ----------------------------------------------------------------
__global__ void prep_kernel(const float* __restrict__ f0, const float* __restrict__ fr,
                            const float* __restrict__ actw) {
    int idx = blockIdx.x * 256 + threadIdx.x;
    if (idx < 307200) {
        int co = idx & 63, r = idx >> 6;
        int tap = r % 25; r /= 25;
        int ci = r & 63, l = r >> 6;
        int u = tap / 5, v = tap % 5, flip = (4 - u) * 5 + (4 - v);
        float wf = fr[((l * 64 + co) * 64 + ci) * 25 + tap];
        float wb = fr[((l * 64 + ci) * 64 + co) * 25 + flip];
        int ck = ci >> 4, c16 = ci & 15;
        size_t of = ((((size_t)(l * 4 + ck) * 25 + tap) * 2) * 64 + co) * 16 + c16;
        size_t ob = (((((size_t)(3 + l) * 4 + ck) * 25 + tap) * 2) * 64 + co) * 16 + c16;
        bf fh = __float2bfloat16_rn(wf), bh = __float2bfloat16_rn(wb);
        g_wbf[of] = fh;        g_wbf[of + 1024] = __float2bfloat16_rn(wf - __bfloat162float(fh));
        g_wbf[ob] = bh;        g_wbf[ob + 1024] = __float2bfloat16_rn(wb - __bfloat162float(bh));
    }
    if (idx < 1600) {
        int co = idx & 63, uv = idx >> 6;
        g_w0[uv * 64 + co] = f0[co * 25 + uv];
        int a = idx / 25, q = idx % 25, u = q / 5, v = q % 5;
        g_w0b[a * 25 + q] = f0[a * 25 + (4 - u) * 5 + (4 - v)];
    }
    if (idx < 20480) {
        int q = (idx % 80) - 8, lc = idx / 80;
        g_actp[idx] = (q >= 0 && q < 63) ? actw[lc * 63 + q] : 0.f;
    }
}

// ---- mma.sync conv layer (64->64, bf16 hi/lo x 3 products) ---------------
// CTA: one output row y (128 px x 64 co). Warp: 32px x 32co. 3 CTAs/SM.
// A slab: [half2][row5][x132][ci16], 32B px-rows, k8 granule XOR-swizzled
// with px bit2 (conflict-free ldmatrix at any alignment). B: 5-tap groups
// (one kernel row: u=group, v=lane-in-group), co-bit2 XOR swizzle.
template <bool BWD, bool STORE_T>
__global__ __launch_bounds__(256, 3)
void mma_conv(const bf* __restrict__ inH, const bf* __restrict__ inL,
              const bf* __restrict__ wbf, const float* __restrict__ bias,
              const float* __restrict__ actp, const float* __restrict__ tg,
              float* __restrict__ tout, bf* __restrict__ outH, bf* __restrict__ outL) {
    extern __shared__ __align__(16) char smem[];
    const int tid = threadIdx.x, w = tid >> 5, lane = tid & 31;
    const int n = blockIdx.z, y = blockIdx.x;
    const int x0 = (w & 3) * 32, co0 = (w >> 2) * 32;

    const u32 base = s2u(smem);
    const int xl = x0 + (lane & 15);            // px coordinate for A rows
    const u32 k16 = ((lane >> 4) & 1) << 4;     // A k8 granule (16B)
    u32 aR[2][2];                                // [half][mt], no k8 term
#pragma unroll
    for (int h = 0; h < 2; h++)
#pragma unroll
        for (int mt = 0; mt < 2; mt++)
            aR[h][mt] = base + h * 21120 + (u32)(xl + 16 * mt) * 32;

    u32 bSt[2][2];
#pragma unroll
    for (int h = 0; h < 2; h++)
#pragma unroll
        for (int p = 0; p < 2; p++) {
            int co = co0 + 16 * p + ((lane >> 4) << 3) + (lane & 7);
            int k8 = (lane >> 3) & 1;
            bSt[h][p] = base + BB + h * 2048 + co * 32 +
                        ((k8 ^ ((co >> 2) & 1)) << 4);
        }

    float acc[2][4][4];
#pragma unroll
    for (int i = 0; i < 2; i++)
#pragma unroll
        for (int j = 0; j < 4; j++)
#pragma unroll
            for (int k = 0; k < 4; k++) acc[i][j][k] = 0.f;

    const size_t imgbase = (size_t)n * HW * 64;

    for (int ck = 0; ck < 4; ck++) {
        for (int g = 0; g < 5; g++) {            // group g = kernel row u
            __syncthreads();
            if (g == 0) {
                // stage A: 2640 uint4 (2 halves x 660 positions x 2 k8-granules)
                const bf* pH = inH + imgbase + ck * 16;
                const bf* pL = inL + imgbase + ck * 16;
                for (int i = tid; i < 2640; i += 256) {
                    int q = i & 1, p = i >> 1;
                    int h = (p >= 660) ? 1 : 0;
                    int pos = p - h * 660;
                    int r = pos / 132, x = pos - r * 132;
                    int gy = y + r - 2, gx = x - 2;
                    const bf* src = h ? pL : pH;
                    uint4 v;
                    if (BWD) {
                        if (gy >= 0 && gy < 128 && gx >= 0 && gx < 128)
                            v = *(const uint4*)(src + (size_t)(gy * 128 + gx) * 64 + q * 8);
                        else v = make_uint4(0, 0, 0, 0);
                    } else {
                        int cy = min(max(gy, 0), 127), cx = min(max(gx, 0), 127);
                        v = *(const uint4*)(src + (size_t)(cy * 128 + cx) * 64 + q * 8);
                    }
                    int qs = q ^ ((x >> 2) & 1);
                    *(uint4*)(smem + h * 21120 + pos * 32 + qs * 16) = v;
                }
            }
            // stage B group: 5 taps x 4096B = 1280 uint4, swizzled per 128-blk
            {
                const uint4* bs = (const uint4*)(wbf + (size_t)ck * 51200 + (size_t)g * 10240);
                uint4* bd = (uint4*)(smem + BB);
                for (int i = tid; i < 1280; i += 256) {
                    int j = i & 127;
                    int js = j ^ ((j >> 3) & 1);
                    bd[(i & ~127) | js] = bs[i];
                }
            }
            __syncthreads();
#pragma unroll
            for (int tl = 0; tl < 5; tl++) {     // tl = kernel col v
                u32 sh32 = (u32)(g * 132 + tl) * 32;
                u32 b16 = (u32)(((xl + tl) >> 2) & 1) << 4;
                u32 aoff = sh32 + (k16 ^ b16);
                u32 Ah0[4], Ah1[4], Al0[4], Al1[4];
                ldsm4(Ah0, aR[0][0] + aoff); ldsm4(Ah1, aR[0][1] + aoff);
                ldsm4(Al0, aR[1][0] + aoff); ldsm4(Al1, aR[1][1] + aoff);
                u32 bt = (u32)tl * 4096;
                u32 Bh[2][4], Bl[2][4];
                ldsm4(Bh[0], bSt[0][0] + bt); ldsm4(Bh[1], bSt[0][1] + bt);
                ldsm4(Bl[0], bSt[1][0] + bt); ldsm4(Bl[1], bSt[1][1] + bt);
#pragma unroll
                for (int nt = 0; nt < 4; nt++) {
                    const u32* bh = &Bh[nt >> 1][(nt & 1) * 2];
                    const u32* bl = &Bl[nt >> 1][(nt & 1) * 2];
                    mma16816(acc[0][nt], Ah0, bh);
                    mma16816(acc[0][nt], Ah0, bl);
                    mma16816(acc[0][nt], Al0, bh);
                    mma16816(acc[1][nt], Ah1, bh);
                    mma16816(acc[1][nt], Ah1, bl);
                    mma16816(acc[1][nt], Al1, bh);
                }
            }
        }
    }

    // epilogue: act table into smem (A region), activate/gate, channel-last st
    __syncthreads();
    float* sF = (float*)smem;
    for (int i = tid; i < 5120; i += 256) sF[i] = actp[i];
    __syncthreads();

    const int g2 = lane >> 2, t2 = (lane & 3) * 2;
#pragma unroll
    for (int mt = 0; mt < 2; mt++)
#pragma unroll
        for (int nt = 0; nt < 4; nt++) {
            const float* d = acc[mt][nt];
            int pxb = x0 + 16 * mt + g2, cb = co0 + 8 * nt + t2;
            const float* wr0 = sF + cb * 80 + 8;
            const float* wr1 = wr0 + 80;
#pragma unroll
            for (int rr = 0; rr < 2; rr++) {
                int px = pxb + rr * 8;
                float v0 = d[rr * 2 + 0], v1 = d[rr * 2 + 1];
                size_t p = ((size_t)n * HW + (size_t)y * 128 + px) * 64 + cb;
                float r0, r1;
                if (BWD) {
                    float2 tv = *(const float2*)(tg + p);
                    r0 = v0 * act_grad(tv.x, wr0);
                    r1 = v1 * act_grad(tv.y, wr1);
                } else {
                    v0 += bias[cb]; v1 += bias[cb + 1];
                    if (STORE_T) *(float2*)(tout + p) = make_float2(v0, v1);
                    r0 = act_fwd(v0, wr0);
                    r1 = act_fwd(v1, wr1);
                }
                bf h0 = __float2bfloat16_rn(r0), h1 = __float2bfloat16_rn(r1);
                __nv_bfloat162 hh; hh.x = h0; hh.y = h1;
                *(__nv_bfloat162*)(outH + p) = hh;
                __nv_bfloat162 ll;
                ll.x = __float2bfloat16_rn(r0 - __bfloat162float(h0));
                ll.y = __float2bfloat16_rn(r1 - __bfloat162float(h1));
                *(__nv_bfloat162*)(outL + p) = ll;
            }
        }
}

// ---- conv0: 1->64 scalar (rep-pad, x255, bias, t0, act), channel-last out
__global__ __launch_bounds__(256)
void conv0_kernel(const float* __restrict__ x, const float* __restrict__ bias,
                  float* __restrict__ tout, bf* __restrict__ outH, bf* __restrict__ outL) {
    __shared__ float s_w[1600], s_act[5120], s_in[432];
    const int tid = threadIdx.x, xx = tid & 31, wid = tid >> 5;
    const int n = blockIdx.z, tx0 = blockIdx.x * 32, ty0 = blockIdx.y * 8;
    for (int i = tid; i < 1600; i += 256) s_w[i] = g_w0[i];
    for (int i = tid; i < 5120; i += 256) s_act[i] = g_actp[i];
    const float* ip = x + (size_t)n * HW;
    for (int i = tid; i < 432; i += 256) {
        int py = i / 36, px = i - py * 36;
        int gy = min(max(ty0 + py - 2, 0), 127), gx = min(max(tx0 + px - 2, 0), 127);
        s_in[i] = ip[gy * 128 + gx] * 255.f;
    }
    __syncthreads();
    float acc[64];
#pragma unroll
    for (int i = 0; i < 64; i++) acc[i] = 0.f;
#pragma unroll
    for (int u = 0; u < 5; u++)
#pragma unroll
        for (int v = 0; v < 5; v++) {
            const float4* wq = (const float4*)&s_w[(u * 5 + v) * 64 + wid * 8];
            float4 wa = wq[0], wb = wq[1];
#pragma unroll
            for (int yy = 0; yy < 8; yy++) {
                float iv = s_in[(yy + u) * 36 + xx + v];
                acc[yy * 8 + 0] += iv * wa.x;  acc[yy * 8 + 1] += iv * wa.y;
                acc[yy * 8 + 2] += iv * wa.z;  acc[yy * 8 + 3] += iv * wa.w;
                acc[yy * 8 + 4] += iv * wb.x;  acc[yy * 8 + 5] += iv * wb.y;
                acc[yy * 8 + 6] += iv * wb.z;  acc[yy * 8 + 7] += iv * wb.w;
            }
        }
#pragma unroll
    for (int c = 0; c < 8; c += 2) {
        int co = wid * 8 + c;
        const float* wr0 = &s_act[co * 80 + 8];
        const float* wr1 = wr0 + 80;
        float b0 = bias[co], b1 = bias[co + 1];
#pragma unroll
        for (int yy = 0; yy < 8; yy++) {
            size_t p = ((size_t)n * HW + (size_t)(ty0 + yy) * 128 + tx0 + xx) * 64 + co;
            float v0 = acc[yy * 8 + c] + b0, v1 = acc[yy * 8 + c + 1] + b1;
            *(float2*)(tout + p) = make_float2(v0, v1);
            float r0 = act_fwd(v0, wr0), r1 = act_fwd(v1, wr1);
            bf h0 = __float2bfloat16_rn(r0), h1 = __float2bfloat16_rn(r1);
            __nv_bfloat162 hh; hh.x = h0; hh.y = h1;
            *(__nv_bfloat162*)(outH + p) = hh;
            __nv_bfloat162 ll;
            ll.x = __float2bfloat16_rn(r0 - __bfloat162float(h0));
            ll.y = __float2bfloat16_rn(r1 - __bfloat162float(h1));
            *(__nv_bfloat162*)(outL + p) = ll;
        }
    }
}

// ---- final: crop(conv_t(in, f0)) 64->1 + combine (channel-last input) ----
__global__ __launch_bounds__(256)
void final_kernel(const bf* __restrict__ inH, const bf* __restrict__ inL,
                  const float* __restrict__ xin, const float* __restrict__ yin,
                  const float* __restrict__ lam, float* __restrict__ out) {
    __shared__ float s_w[1600], s_in[16 * 432];
    const int tid = threadIdx.x, x = tid & 31, yy = tid >> 5;
    const int n = blockIdx.z, tx0 = blockIdx.x * 32, ty0 = blockIdx.y * 8;
    for (int i = tid; i < 1600; i += 256) s_w[i] = g_w0b[i];
    float acc = 0.f;
    for (int c0 = 0; c0 < 64; c0 += 16) {
        __syncthreads();
        for (int i = tid; i < 6912; i += 256) {
            int cc = i & 15, j = i >> 4;
            int py = j / 36, px = j - py * 36;
            int gy = ty0 + py - 2, gx = tx0 + px - 2;
            float vv = 0.f;
            if (gy >= 0 && gy < 128 && gx >= 0 && gx < 128) {
                size_t o = ((size_t)n * HW + (size_t)gy * 128 + gx) * 64 + c0 + cc;
                vv = __bfloat162float(inH[o]) + __bfloat162float(inL[o]);
            }
            s_in[cc * 432 + j] = vv;
        }
        __syncthreads();
#pragma unroll
        for (int cc = 0; cc < 16; cc++) {
            const float* wp = &s_w[(c0 + cc) * 25];
            const float* pin = s_in + cc * 432;
#pragma unroll
            for (int u = 0; u < 5; u++)
#pragma unroll
                for (int v = 0; v < 5; v++)
                    acc += pin[(yy + u) * 36 + x + v] * wp[u * 5 + v];
        }
    }
    size_t idx = (size_t)n * HW + (size_t)(ty0 + yy) * 128 + tx0 + x;
    float xv = xin[idx], yv = yin[idx];
    out[idx] = xv - acc * (1.f / 255.f) - __expf(lam[0]) * (xv - yv);
}

// ---- launch --------------------------------------------------------------
extern "C" void kernel_launch(void* const* d_in, const int* in_sizes, int n_in,
                              void* d_out, int out_size) {
    const float *x = nullptr, *y = nullptr, *lam = nullptr, *f0 = nullptr,
                *fr = nullptr, *bias = nullptr, *actw = nullptr;
    for (int i = 0; i < n_in; i++) {
        const float* p = (const float*)d_in[i];
        switch (in_sizes[i]) {
            case 65536: if (!x) x = p; else y = p; break;
            case 1: lam = p; break;
            case 1600: f0 = p; break;
            case 307200: fr = p; break;
            case 256: bias = p; break;
            case 16128: actw = p; break;
            default: break;
        }
    }
    void *pAh, *pAl, *pBh, *pBl, *pT, *pW, *pact;
    cudaGetSymbolAddress(&pAh, g_Ah); cudaGetSymbolAddress(&pAl, g_Al);
    cudaGetSymbolAddress(&pBh, g_Bh); cudaGetSymbolAddress(&pBl, g_Bl);
    cudaGetSymbolAddress(&pT, g_T);   cudaGetSymbolAddress(&pW, g_wbf);
    cudaGetSymbolAddress(&pact, g_actp);
    bf *Ah = (bf*)pAh, *Al = (bf*)pAl, *Bh = (bf*)pBh, *Bl = (bf*)pBl;
    float *T = (float*)pT, *act = (float*)pact;
    bf *W = (bf*)pW;

    cudaFuncSetAttribute(mma_conv<false, true >, cudaFuncAttributeMaxDynamicSharedMemorySize, DSMEM);
    cudaFuncSetAttribute(mma_conv<false, false>, cudaFuncAttributeMaxDynamicSharedMemorySize, DSMEM);
    cudaFuncSetAttribute(mma_conv<true,  false>, cudaFuncAttributeMaxDynamicSharedMemorySize, DSMEM);

    dim3 gs(4, 16, 4), gm(128, 1, 4), blk(256);
    prep_kernel<<<1200, 256>>>(f0, fr, actw);
    conv0_kernel<<<gs, blk>>>(x, bias, T, Ah, Al);
    // forward layers 1..3 (weights ld0..2)
    mma_conv<false, true ><<<gm, blk, DSMEM>>>(Ah, Al, W,            bias + 64,  act + 5120,     nullptr, T + (size_t)NCHW, Bh, Bl);
    mma_conv<false, true ><<<gm, blk, DSMEM>>>(Bh, Bl, W + LWBF,     bias + 128, act + 2 * 5120, nullptr, T + 2ull * NCHW,  Ah, Al);
    mma_conv<false, false><<<gm, blk, DSMEM>>>(Ah, Al, W + 2 * LWBF, bias + 192, act + 3 * 5120, nullptr, nullptr,          Bh, Bl);
    // backward: convT(w3) gate t2, convT(w2) gate t1, convT(w1) gate t0
    mma_conv<true, false><<<gm, blk, DSMEM>>>(Bh, Bl, W + 5 * LWBF, nullptr, act + 2 * 5120, T + 2ull * NCHW,  nullptr, Ah, Al);
    mma_conv<true, false><<<gm, blk, DSMEM>>>(Ah, Al, W + 4 * LWBF, nullptr, act + 5120,     T + (size_t)NCHW, nullptr, Bh, Bl);
    mma_conv<true, false><<<gm, blk, DSMEM>>>(Bh, Bl, W + 3 * LWBF, nullptr, act,            T,                nullptr, Ah, Al);
    final_kernel<<<gs, blk>>>(Ah, Al, x, y, lam, (float*)d_out);
}

// round 16
// speedup vs baseline: 1.1512x; 1.0778x over previous
#include <cuda_runtime.h>
#include <cuda_bf16.h>
#include <cstdint>
#include <cstddef>

#define HW 16384
#define NCHW 4194304
#define LWBF 204800            // bf16 per layer-dir weight blob
#define BB 42240               // B buffers offset (A slab is 42240 B)
#define DSMEM 83200            // A (42240) + 2 x B group of 5 taps (2x20480)
typedef uint32_t u32;
typedef __nv_bfloat16 bf;

// channel-last [n][y][x][c] hi/lo activation tensors
__device__ bf g_Ah[NCHW], g_Al[NCHW], g_Bh[NCHW], g_Bl[NCHW];
__device__ float g_T[3ull * NCHW];   // t0..t2, channel-last fp32
__device__ bf g_wbf[6 * LWBF];       // [ld6][chunk4][tap25][half2][co64][ci16]
__device__ float g_w0[1600];         // conv0 [uv][co]
__device__ float g_w0b[1600];        // final convT [a][u][v] flipped
__device__ float g_actp[20480];      // [l4][c64][80], data at +8

// ---- helpers -------------------------------------------------------------
__device__ __forceinline__ u32 s2u(const void* p) {
    u32 a; asm("{.reg .u64 t; cvta.to.shared.u64 t,%1; cvt.u32.u64 %0,t;}" : "=r"(a) : "l"(p));
    return a;
}
__device__ __forceinline__ void ldsm4(u32* r, u32 a) {
    asm volatile("ldmatrix.sync.aligned.m8n8.x4.shared.b16 {%0,%1,%2,%3},[%4];"
                 : "=r"(r[0]), "=r"(r[1]), "=r"(r[2]), "=r"(r[3]) : "r"(a));
}
__device__ __forceinline__ void mma16816(float* d, const u32* a, const u32* b) {
    asm volatile("mma.sync.aligned.m16n8k16.row.col.f32.bf16.bf16.f32 "
                 "{%0,%1,%2,%3},{%4,%5,%6,%7},{%8,%9},{%0,%1,%2,%3};"
                 : "+f"(d[0]), "+f"(d[1]), "+f"(d[2]), "+f"(d[3])
                 : "r"(a[0]), "r"(a[1]), "r"(a[2]), "r"(a[3]), "r"(b[0]), "r"(b[1]));
}
__device__ __forceinline__ void cpasync16(u32 dst, const void* src) {
    asm volatile("cp.async.cg.shared.global [%0], [%1], 16;" :: "r"(dst), "l"(src));
}
#define CP_COMMIT() asm volatile("cp.async.commit_group;" ::: "memory")
#define CP_WAIT1()  asm volatile("cp.async.wait_group 1;" ::: "memory")

// ---- RBF activation, windowed |k|<=6 recurrence (verified R2) ------------
__device__ __forceinline__ float act_fwd(float v, const float* __restrict__ wr) {
    float pf = rintf((v + 310.f) * 0.1f); pf = fminf(fmaxf(pf, 0.f), 62.f);
    float d0 = v + 310.f - 10.f * pf; d0 = fminf(fmaxf(d0, -55.f), 55.f);
    float a = __expf(0.1f * d0), ai = __expf(-0.1f * d0), E0 = __expf(-0.005f * d0 * d0);
    const float* w = wr + (int)pf;
    const float CK[7] = {0.f, 0.60653066f, 0.22313016f, 0.082084999f, 0.030197383f, 0.011108997f, 0.0040867714f};
    float s = w[0], up = 1.f, un = 1.f;
#pragma unroll
    for (int k = 1; k <= 6; k++) { up *= a * CK[k]; un *= ai * CK[k]; s += w[k] * up + w[-k] * un; }
    return E0 * s;
}
__device__ __forceinline__ float act_grad(float v, const float* __restrict__ wr) {
    float pf = rintf((v + 310.f) * 0.1f); pf = fminf(fmaxf(pf, 0.f), 62.f);
    float d0 = v + 310.f - 10.f * pf; d0 = fminf(fmaxf(d0, -55.f), 55.f);
    float a = __expf(0.1f * d0), ai = __expf(-0.1f * d0), E0 = __expf(-0.005f * d0 * d0);
    const float* w = wr + (int)pf;
    const float CK[7] = {0.f, 0.60653066f, 0.22313016f, 0.082084999f, 0.030197383f, 0.011108997f, 0.0040867714f};
    float s = w[0], s1 = 0.f, up = 1.f, un = 1.f;
#pragma unroll
    for (int k = 1; k <= 6; k++) {
        up *= a * CK[k]; un *= ai * CK[k];
        float tp = w[k] * up, tm = w[-k] * un;
        s += tp + tm; s1 += (float)k * (tp - tm);
    }
    return -0.01f * E0 * (d0 * s - 10.f * s1);
}

// ---- prep ----------------------------------------------------------------
__global__ void prep_kernel(const float* __restrict__ f0, const float* __restrict__ fr,
                            const float* __restrict__ actw) {
    int idx = blockIdx.x * 256 + threadIdx.x;
    if (idx < 307200) {
        int co = idx & 63, r = idx >> 6;
        int tap = r % 25; r /= 25;
        int ci = r & 63, l = r >> 6;
        int u = tap / 5, v = tap % 5, flip = (4 - u) * 5 + (4 - v);
        float wf = fr[((l * 64 + co) * 64 + ci) * 25 + tap];
        float wb = fr[((l * 64 + ci) * 64 + co) * 25 + flip];
        int ck = ci >> 4, c16 = ci & 15;
        size_t of = ((((size_t)(l * 4 + ck) * 25 + tap) * 2) * 64 + co) * 16 + c16;
        size_t ob = (((((size_t)(3 + l) * 4 + ck) * 25 + tap) * 2) * 64 + co) * 16 + c16;
        bf fh = __float2bfloat16_rn(wf), bh = __float2bfloat16_rn(wb);
        g_wbf[of] = fh;        g_wbf[of + 1024] = __float2bfloat16_rn(wf - __bfloat162float(fh));
        g_wbf[ob] = bh;        g_wbf[ob + 1024] = __float2bfloat16_rn(wb - __bfloat162float(bh));
    }
    if (idx < 1600) {
        int co = idx & 63, uv = idx >> 6;
        g_w0[uv * 64 + co] = f0[co * 25 + uv];
        int a = idx / 25, q = idx % 25, u = q / 5, v = q % 5;
        g_w0b[a * 25 + q] = f0[a * 25 + (4 - u) * 5 + (4 - v)];
    }
    if (idx < 20480) {
        int q = (idx % 80) - 8, lc = idx / 80;
        g_actp[idx] = (q >= 0 && q < 63) ? actw[lc * 63 + q] : 0.f;
    }
}

// ---- mma.sync conv layer (64->64, bf16 hi/lo x 3 products) ---------------
// CTA: one output row y (128 px x 64 co). Warp: 32px x 32co. 2 CTAs/SM.
// B weight groups (5 taps = one kernel row) double-buffered via cp.async:
// group s+1 prefetched during mma of group s -> L2 latency off critical path.
// A slab: [half2][row5][x132][ci16], 32B px-rows, k8 XOR-swizzled with px bit2.
template <bool BWD, bool STORE_T>
__global__ __launch_bounds__(256, 2)
void mma_conv(const bf* __restrict__ inH, const bf* __restrict__ inL,
              const bf* __restrict__ wbf, const float* __restrict__ bias,
              const float* __restrict__ actp, const float* __restrict__ tg,
              float* __restrict__ tout, bf* __restrict__ outH, bf* __restrict__ outL) {
    extern __shared__ __align__(16) char smem[];
    const int tid = threadIdx.x, w = tid >> 5, lane = tid & 31;
    const int n = blockIdx.z, y = blockIdx.x;
    const int x0 = (w & 3) * 32, co0 = (w >> 2) * 32;

    const u32 base = s2u(smem);
    const int xl = x0 + (lane & 15);            // px coordinate for A rows
    const u32 k16 = ((lane >> 4) & 1) << 4;     // A k8 granule (16B)
    u32 aR[2][2];
#pragma unroll
    for (int h = 0; h < 2; h++)
#pragma unroll
        for (int mt = 0; mt < 2; mt++)
            aR[h][mt] = base + h * 21120 + (u32)(xl + 16 * mt) * 32;

    u32 bSt[2][2];
#pragma unroll
    for (int h = 0; h < 2; h++)
#pragma unroll
        for (int p = 0; p < 2; p++) {
            int co = co0 + 16 * p + ((lane >> 4) << 3) + (lane & 7);
            int k8 = (lane >> 3) & 1;
            bSt[h][p] = base + BB + h * 2048 + co * 32 +
                        ((k8 ^ ((co >> 2) & 1)) << 4);
        }

    float acc[2][4][4];
#pragma unroll
    for (int i = 0; i < 2; i++)
#pragma unroll
        for (int j = 0; j < 4; j++)
#pragma unroll
            for (int k = 0; k < 4; k++) acc[i][j][k] = 0.f;

    const size_t imgbase = (size_t)n * HW * 64;

    // B prefetch for phase s (s = ck*5 + g) into buffer s&1
    auto prefetchB = [&](int s) {
        if (s >= 20) return;
        int ck = s / 5, g = s % 5;
        const uint4* bs = (const uint4*)(wbf + (size_t)ck * 51200 + (size_t)g * 10240);
        u32 bd = base + BB + (u32)(s & 1) * 20480;
        for (int i = tid; i < 1280; i += 256) {
            int j = i & 127;
            int js = j ^ ((j >> 3) & 1);
            cpasync16(bd + (u32)(((i & ~127) | js) << 4), bs + i);
        }
    };

    prefetchB(0); CP_COMMIT();

    for (int s = 0; s < 20; s++) {
        const int ck = s / 5, g = s - ck * 5;    // g = kernel row u
        if (g == 0) {
            __syncthreads();                      // A slab free (prev ck done)
            // stage A: 2640 uint4 (2 halves x 660 positions x 2 k8-granules)
            const bf* pH = inH + imgbase + ck * 16;
            const bf* pL = inL + imgbase + ck * 16;
            for (int i = tid; i < 2640; i += 256) {
                int q = i & 1, p = i >> 1;
                int h = (p >= 660) ? 1 : 0;
                int pos = p - h * 660;
                int r = pos / 132, x = pos - r * 132;
                int gy = y + r - 2, gx = x - 2;
                const bf* src = h ? pL : pH;
                uint4 v;
                if (BWD) {
                    if (gy >= 0 && gy < 128 && gx >= 0 && gx < 128)
                        v = *(const uint4*)(src + (size_t)(gy * 128 + gx) * 64 + q * 8);
                    else v = make_uint4(0, 0, 0, 0);
                } else {
                    int cy = min(max(gy, 0), 127), cx = min(max(gx, 0), 127);
                    v = *(const uint4*)(src + (size_t)(cy * 128 + cx) * 64 + q * 8);
                }
                int qs = q ^ ((x >> 2) & 1);
                *(uint4*)(smem + h * 21120 + pos * 32 + qs * 16) = v;
            }
        }
        __syncthreads();                          // buf[(s+1)&1] free + A visible
        prefetchB(s + 1); CP_COMMIT();
        CP_WAIT1();                               // buf[s&1] data arrived
        __syncthreads();                          // visibility for all warps

        const u32 bufo = (u32)(s & 1) * 20480;
#pragma unroll
        for (int tl = 0; tl < 5; tl++) {          // tl = kernel col v
            u32 sh32 = (u32)(g * 132 + tl) * 32;
            u32 b16 = (u32)(((xl + tl) >> 2) & 1) << 4;
            u32 aoff = sh32 + (k16 ^ b16);
            u32 Ah0[4], Ah1[4], Al0[4], Al1[4];
            ldsm4(Ah0, aR[0][0] + aoff); ldsm4(Ah1, aR[0][1] + aoff);
            ldsm4(Al0, aR[1][0] + aoff); ldsm4(Al1, aR[1][1] + aoff);
            u32 bt = (u32)tl * 4096 + bufo;
            u32 Bh[2][4], Bl[2][4];
            ldsm4(Bh[0], bSt[0][0] + bt); ldsm4(Bh[1], bSt[0][1] + bt);
            ldsm4(Bl[0], bSt[1][0] + bt); ldsm4(Bl[1], bSt[1][1] + bt);
#pragma unroll
            for (int nt = 0; nt < 4; nt++) {
                const u32* bh = &Bh[nt >> 1][(nt & 1) * 2];
                const u32* bl = &Bl[nt >> 1][(nt & 1) * 2];
                mma16816(acc[0][nt], Ah0, bh);
                mma16816(acc[0][nt], Ah0, bl);
                mma16816(acc[0][nt], Al0, bh);
                mma16816(acc[1][nt], Ah1, bh);
                mma16816(acc[1][nt], Ah1, bl);
                mma16816(acc[1][nt], Al1, bh);
            }
        }
    }

    // epilogue: act table into smem (A region), activate/gate, channel-last st
    __syncthreads();
    float* sF = (float*)smem;
    for (int i = tid; i < 5120; i += 256) sF[i] = actp[i];
    __syncthreads();

    const int g2 = lane >> 2, t2 = (lane & 3) * 2;
#pragma unroll
    for (int mt = 0; mt < 2; mt++)
#pragma unroll
        for (int nt = 0; nt < 4; nt++) {
            const float* d = acc[mt][nt];
            int pxb = x0 + 16 * mt + g2, cb = co0 + 8 * nt + t2;
            const float* wr0 = sF + cb * 80 + 8;
            const float* wr1 = wr0 + 80;
#pragma unroll
            for (int rr = 0; rr < 2; rr++) {
                int px = pxb + rr * 8;
                float v0 = d[rr * 2 + 0], v1 = d[rr * 2 + 1];
                size_t p = ((size_t)n * HW + (size_t)y * 128 + px) * 64 + cb;
                float r0, r1;
                if (BWD) {
                    float2 tv = *(const float2*)(tg + p);
                    r0 = v0 * act_grad(tv.x, wr0);
                    r1 = v1 * act_grad(tv.y, wr1);
                } else {
                    v0 += bias[cb]; v1 += bias[cb + 1];
                    if (STORE_T) *(float2*)(tout + p) = make_float2(v0, v1);
                    r0 = act_fwd(v0, wr0);
                    r1 = act_fwd(v1, wr1);
                }
                bf h0 = __float2bfloat16_rn(r0), h1 = __float2bfloat16_rn(r1);
                __nv_bfloat162 hh; hh.x = h0; hh.y = h1;
                *(__nv_bfloat162*)(outH + p) = hh;
                __nv_bfloat162 ll;
                ll.x = __float2bfloat16_rn(r0 - __bfloat162float(h0));
                ll.y = __float2bfloat16_rn(r1 - __bfloat162float(h1));
                *(__nv_bfloat162*)(outL + p) = ll;
            }
        }
}

// ---- conv0: 1->64 scalar (rep-pad, x255, bias, t0, act), channel-last out
__global__ __launch_bounds__(256)
void conv0_kernel(const float* __restrict__ x, const float* __restrict__ bias,
                  float* __restrict__ tout, bf* __restrict__ outH, bf* __restrict__ outL) {
    __shared__ float s_w[1600], s_act[5120], s_in[432];
    const int tid = threadIdx.x, xx = tid & 31, wid = tid >> 5;
    const int n = blockIdx.z, tx0 = blockIdx.x * 32, ty0 = blockIdx.y * 8;
    for (int i = tid; i < 1600; i += 256) s_w[i] = g_w0[i];
    for (int i = tid; i < 5120; i += 256) s_act[i] = g_actp[i];
    const float* ip = x + (size_t)n * HW;
    for (int i = tid; i < 432; i += 256) {
        int py = i / 36, px = i - py * 36;
        int gy = min(max(ty0 + py - 2, 0), 127), gx = min(max(tx0 + px - 2, 0), 127);
        s_in[i] = ip[gy * 128 + gx] * 255.f;
    }
    __syncthreads();
    float acc[64];
#pragma unroll
    for (int i = 0; i < 64; i++) acc[i] = 0.f;
#pragma unroll
    for (int u = 0; u < 5; u++)
#pragma unroll
        for (int v = 0; v < 5; v++) {
            const float4* wq = (const float4*)&s_w[(u * 5 + v) * 64 + wid * 8];
            float4 wa = wq[0], wb = wq[1];
#pragma unroll
            for (int yy = 0; yy < 8; yy++) {
                float iv = s_in[(yy + u) * 36 + xx + v];
                acc[yy * 8 + 0] += iv * wa.x;  acc[yy * 8 + 1] += iv * wa.y;
                acc[yy * 8 + 2] += iv * wa.z;  acc[yy * 8 + 3] += iv * wa.w;
                acc[yy * 8 + 4] += iv * wb.x;  acc[yy * 8 + 5] += iv * wb.y;
                acc[yy * 8 + 6] += iv * wb.z;  acc[yy * 8 + 7] += iv * wb.w;
            }
        }
#pragma unroll
    for (int c = 0; c < 8; c += 2) {
        int co = wid * 8 + c;
        const float* wr0 = &s_act[co * 80 + 8];
        const float* wr1 = wr0 + 80;
        float b0 = bias[co], b1 = bias[co + 1];
#pragma unroll
        for (int yy = 0; yy < 8; yy++) {
            size_t p = ((size_t)n * HW + (size_t)(ty0 + yy) * 128 + tx0 + xx) * 64 + co;
            float v0 = acc[yy * 8 + c] + b0, v1 = acc[yy * 8 + c + 1] + b1;
            *(float2*)(tout + p) = make_float2(v0, v1);
            float r0 = act_fwd(v0, wr0), r1 = act_fwd(v1, wr1);
            bf h0 = __float2bfloat16_rn(r0), h1 = __float2bfloat16_rn(r1);
            __nv_bfloat162 hh; hh.x = h0; hh.y = h1;
            *(__nv_bfloat162*)(outH + p) = hh;
            __nv_bfloat162 ll;
            ll.x = __float2bfloat16_rn(r0 - __bfloat162float(h0));
            ll.y = __float2bfloat16_rn(r1 - __bfloat162float(h1));
            *(__nv_bfloat162*)(outL + p) = ll;
        }
    }
}

// ---- final: crop(conv_t(in, f0)) 64->1 + combine (channel-last input) ----
__global__ __launch_bounds__(256)
void final_kernel(const bf* __restrict__ inH, const bf* __restrict__ inL,
                  const float* __restrict__ xin, const float* __restrict__ yin,
                  const float* __restrict__ lam, float* __restrict__ out) {
    __shared__ float s_w[1600], s_in[16 * 432];
    const int tid = threadIdx.x, x = tid & 31, yy = tid >> 5;
    const int n = blockIdx.z, tx0 = blockIdx.x * 32, ty0 = blockIdx.y * 8;
    for (int i = tid; i < 1600; i += 256) s_w[i] = g_w0b[i];
    float acc = 0.f;
    for (int c0 = 0; c0 < 64; c0 += 16) {
        __syncthreads();
        for (int i = tid; i < 6912; i += 256) {
            int cc = i & 15, j = i >> 4;
            int py = j / 36, px = j - py * 36;
            int gy = ty0 + py - 2, gx = tx0 + px - 2;
            float vv = 0.f;
            if (gy >= 0 && gy < 128 && gx >= 0 && gx < 128) {
                size_t o = ((size_t)n * HW + (size_t)gy * 128 + gx) * 64 + c0 + cc;
                vv = __bfloat162float(inH[o]) + __bfloat162float(inL[o]);
            }
            s_in[cc * 432 + j] = vv;
        }
        __syncthreads();
#pragma unroll
        for (int cc = 0; cc < 16; cc++) {
            const float* wp = &s_w[(c0 + cc) * 25];
            const float* pin = s_in + cc * 432;
#pragma unroll
            for (int u = 0; u < 5; u++)
#pragma unroll
                for (int v = 0; v < 5; v++)
                    acc += pin[(yy + u) * 36 + x + v] * wp[u * 5 + v];
        }
    }
    size_t idx = (size_t)n * HW + (size_t)(ty0 + yy) * 128 + tx0 + x;
    float xv = xin[idx], yv = yin[idx];
    out[idx] = xv - acc * (1.f / 255.f) - __expf(lam[0]) * (xv - yv);
}

// ---- launch --------------------------------------------------------------
extern "C" void kernel_launch(void* const* d_in, const int* in_sizes, int n_in,
                              void* d_out, int out_size) {
    const float *x = nullptr, *y = nullptr, *lam = nullptr, *f0 = nullptr,
                *fr = nullptr, *bias = nullptr, *actw = nullptr;
    for (int i = 0; i < n_in; i++) {
        const float* p = (const float*)d_in[i];
        switch (in_sizes[i]) {
            case 65536: if (!x) x = p; else y = p; break;
            case 1: lam = p; break;
            case 1600: f0 = p; break;
            case 307200: fr = p; break;
            case 256: bias = p; break;
            case 16128: actw = p; break;
            default: break;
        }
    }
    void *pAh, *pAl, *pBh, *pBl, *pT, *pW, *pact;
    cudaGetSymbolAddress(&pAh, g_Ah); cudaGetSymbolAddress(&pAl, g_Al);
    cudaGetSymbolAddress(&pBh, g_Bh); cudaGetSymbolAddress(&pBl, g_Bl);
    cudaGetSymbolAddress(&pT, g_T);   cudaGetSymbolAddress(&pW, g_wbf);
    cudaGetSymbolAddress(&pact, g_actp);
    bf *Ah = (bf*)pAh, *Al = (bf*)pAl, *Bh = (bf*)pBh, *Bl = (bf*)pBl;
    float *T = (float*)pT, *act = (float*)pact;
    bf *W = (bf*)pW;

    cudaFuncSetAttribute(mma_conv<false, true >, cudaFuncAttributeMaxDynamicSharedMemorySize, DSMEM);
    cudaFuncSetAttribute(mma_conv<false, false>, cudaFuncAttributeMaxDynamicSharedMemorySize, DSMEM);
    cudaFuncSetAttribute(mma_conv<true,  false>, cudaFuncAttributeMaxDynamicSharedMemorySize, DSMEM);

    dim3 gs(4, 16, 4), gm(128, 1, 4), blk(256);
    prep_kernel<<<1200, 256>>>(f0, fr, actw);
    conv0_kernel<<<gs, blk>>>(x, bias, T, Ah, Al);
    // forward layers 1..3 (weights ld0..2)
    mma_conv<false, true ><<<gm, blk, DSMEM>>>(Ah, Al, W,            bias + 64,  act + 5120,     nullptr, T + (size_t)NCHW, Bh, Bl);
    mma_conv<false, true ><<<gm, blk, DSMEM>>>(Bh, Bl, W + LWBF,     bias + 128, act + 2 * 5120, nullptr, T + 2ull * NCHW,  Ah, Al);
    mma_conv<false, false><<<gm, blk, DSMEM>>>(Ah, Al, W + 2 * LWBF, bias + 192, act + 3 * 5120, nullptr, nullptr,          Bh, Bl);
    // backward: convT(w3) gate t2, convT(w2) gate t1, convT(w1) gate t0
    mma_conv<true, false><<<gm, blk, DSMEM>>>(Bh, Bl, W + 5 * LWBF, nullptr, act + 2 * 5120, T + 2ull * NCHW,  nullptr, Ah, Al);
    mma_conv<true, false><<<gm, blk, DSMEM>>>(Ah, Al, W + 4 * LWBF, nullptr, act + 5120,     T + (size_t)NCHW, nullptr, Bh, Bl);
    mma_conv<true, false><<<gm, blk, DSMEM>>>(Bh, Bl, W + 3 * LWBF, nullptr, act,            T,                nullptr, Ah, Al);
    final_kernel<<<gs, blk>>>(Ah, Al, x, y, lam, (float*)d_out);
}